// round 7
// baseline (speedup 1.0000x reference)
#include <cuda_runtime.h>
#include <cuda_bf16.h>
#include <cub/block/block_radix_sort.cuh>

#define N 8192
#define ROWLEN 85
#define NCLS 80
#define CAP 512
#define MW 16            // CAP/32 suppression-mask words
#define FT 512           // fused-kernel threads
#define NQ 4             // sort quarters
#define QS 2048          // rows per quarter

__device__ unsigned g_skey[N];        // ~float_bits(score); ascending == score desc
__device__ unsigned g_pack[N];        // row<<7 | cat
__device__ unsigned g_qkeys[NQ][QS];  // per-quarter sorted keys (ascending)
__device__ int g_qpos[N];             // row -> position within its quarter
__device__ int g_rank[N];             // row -> global sorted position
__device__ float g_keepf[N];          // keep flag by original row (1.0 / 0.0)

// ---------------------------------------------------------------------------
// K1: per-row class argmax + combined score -> (key, packed row|cat).
// redux.sync replaces the serial shfl reduction chain.
// ---------------------------------------------------------------------------
__global__ void score_kernel(const float* __restrict__ X) {
    int warp = (blockIdx.x * blockDim.x + threadIdx.x) >> 5;
    int lane = threadIdx.x & 31;
    if (warp >= N) return;
    const float* row = X + (long)warp * ROWLEN;

    float v0 = row[5 + lane];
    float v1 = row[37 + lane];
    float v2 = row[69 + lane];          // lanes 16..31 out of range guarded below
    float best = v0; int bi = lane;
    if (v1 > best) { best = v1; bi = lane + 32; }
    if (lane < 16 && v2 > best) { best = v2; bi = lane + 64; }

    unsigned bb = __float_as_uint(best);          // nonneg -> monotone
    unsigned vmax = __reduce_max_sync(0xffffffffu, bb);
    int cand = (bb == vmax) ? bi : 0x7fffffff;    // smallest class wins ties
    int bimin = __reduce_min_sync(0xffffffffu, cand);

    if (lane == 0) {
        float score = row[4] * __uint_as_float(vmax);  // in [0, 1)
        g_skey[warp] = ~__float_as_uint(score);        // monotone flip
        g_pack[warp] = ((unsigned)warp << 7) | (unsigned)bimin;
    }
}

// ---------------------------------------------------------------------------
// K2 (fused): blocks 0..3 = stable radix sort of one 2048-row quarter each;
// blocks 4..83 = per-class greedy NMS. Class offsets in the reference make
// cross-class IoU exactly 0, so suppression decomposes per class; each class
// block compacts + locally sorts its own entries, independent of the quarters.
// ---------------------------------------------------------------------------
typedef cub::BlockRadixSort<unsigned, FT, QS / FT, unsigned, 5> BlockSortT;

struct NmsShared {
    unsigned long long keys[CAP];
    float4 box[CAP];
    float area[CAP];
    unsigned mask[CAP * MW];
    unsigned sup[MW];
    int cnt;
};

__global__ void __launch_bounds__(FT, 1)
sortnms_kernel(const float* __restrict__ X) {
    extern __shared__ __align__(16) char sm[];
    int t = threadIdx.x;

    if (blockIdx.x < NQ) {
        // ----- quarter sort: 30 significant key bits, 6 passes of 5 bits -----
        const int IPT = QS / FT;   // 4
        int q = blockIdx.x;
        int qbase = q * QS;
        BlockSortT::TempStorage& temp =
            *reinterpret_cast<BlockSortT::TempStorage*>(sm);
        unsigned keys[IPT], vals[IPT];
        #pragma unroll
        for (int l = 0; l < IPT; l++) {
            int r = qbase + t * IPT + l;
            keys[l] = g_skey[r];
            vals[l] = g_pack[r];
        }
        BlockSortT(temp).Sort(keys, vals, 0, 30);   // stable LSD radix
        #pragma unroll
        for (int l = 0; l < IPT; l++) {
            int p = t * IPT + l;
            g_qkeys[q][p] = keys[l];
            g_qpos[vals[l] >> 7] = p;
        }
        return;
    }

    // ----- per-class NMS -----
    NmsShared& S = *reinterpret_cast<NmsShared*>(sm);
    unsigned c = blockIdx.x - NQ;
    int lane = t & 31, w = t >> 5;

    if (t == 0) S.cnt = 0;
    S.keys[t] = 0xFFFFFFFFFFFFFFFFull;                  // pad for bitonic
    __syncthreads();

    // compaction (order irrelevant: local sort fixes it; key64 carries row
    // index for exact stable tie-break identical to the global argsort)
    #pragma unroll
    for (int qq = 0; qq < N / FT; qq++) {
        int r = qq * FT + t;
        unsigned p = g_pack[r];
        if ((p & 127u) == c) {
            int slot = atomicAdd(&S.cnt, 1);
            if (slot < CAP)
                S.keys[slot] = ((unsigned long long)g_skey[r] << 32) | p;
        }
    }
    __syncthreads();
    int m = min(S.cnt, CAP);
    int mw = (m + 31) >> 5;

    // next power of two >= m (>=2): trims bitonic stages to actual class size
    int p2 = 2;
    while (p2 < m) p2 <<= 1;

    // bitonic sort of p2 u64 keys (ascending == score desc, stable by row)
    for (int k = 2; k <= p2; k <<= 1) {
        for (int j = k >> 1; j > 0; j >>= 1) {
            if (t < (p2 >> 1)) {
                int i = ((t & ~(j - 1)) << 1) | (t & (j - 1));
                bool up = ((i & k) == 0);
                unsigned long long a = S.keys[i], b = S.keys[i | j];
                if ((a > b) == up) { S.keys[i] = b; S.keys[i | j] = a; }
            }
            __syncthreads();
        }
    }

    // load boxes in sorted order
    if (t < m) {
        int idx = (int)(((unsigned)(S.keys[t] & 0xFFFFFFFFull)) >> 7);
        const float* row = X + (long)idx * ROWLEN;
        float x1 = row[0], y1 = row[1], x2 = row[2], y2 = row[3];
        S.box[t] = make_float4(x1, y1, x2, y2);
        S.area[t] = (x2 - x1) * (y2 - y1);
    }
    for (int p = t; p < m * MW; p += FT) S.mask[p] = 0u;
    __syncthreads();

    // mask[i] = { j > i : IoU(i,j) > 0.5 } — fully parallel
    for (int i = w; i < m; i += FT / 32) {
        float4 bi = S.box[i];
        float ai = S.area[i];
        for (int j = i + 1 + lane; j < m; j += 32) {
            float4 bj = S.box[j];
            float xx1 = fmaxf(bi.x, bj.x);
            float yy1 = fmaxf(bi.y, bj.y);
            float xx2 = fminf(bi.z, bj.z);
            float yy2 = fminf(bi.w, bj.w);
            float ww = fmaxf(xx2 - xx1, 0.0f);
            float hh = fmaxf(yy2 - yy1, 0.0f);
            float inter = ww * hh;
            float iou = inter / (ai + S.area[j] - inter);
            if (iou > 0.5f) atomicOr(&S.mask[i * MW + (j >> 5)], 1u << (j & 31));
        }
    }
    __syncthreads();

    // serial greedy bit-merge (warp 0; lane l owns suppression word l)
    if (w == 0) {
        unsigned sw = 0;
        for (int i = 0; i < m; i++) {
            unsigned word = __shfl_sync(0xffffffffu, sw, i >> 5);
            if (!((word >> (i & 31)) & 1u)) {
                if (lane < mw) sw |= S.mask[i * MW + lane];
            }
        }
        if (lane < MW) S.sup[lane] = sw;
    }
    __syncthreads();

    if (t < m) {
        int idx = (int)(((unsigned)(S.keys[t] & 0xFFFFFFFFull)) >> 7);
        g_keepf[idx] = ((S.sup[t >> 5] >> (t & 31)) & 1u) ? 0.0f : 1.0f;
    }
}

// ---------------------------------------------------------------------------
// K3: global rank from quarter positions + 3 binary searches per row.
// Quarters are index-contiguous, so the (key asc, idx asc) comparator maps to:
//   q' < q : count elements <= key (ties have smaller idx -> precede)
//   q' > q : count elements <  key
// ---------------------------------------------------------------------------
__global__ void rank_kernel() {
    int r = blockIdx.x * blockDim.x + threadIdx.x;
    if (r >= N) return;
    int q = r / QS;
    unsigned key = g_skey[r];
    int rank = g_qpos[r];
    #pragma unroll
    for (int q2 = 0; q2 < NQ; q2++) {
        if (q2 == q) continue;
        const unsigned* a = g_qkeys[q2];
        int lo = 0, hi = QS;
        if (q2 < q) {
            while (lo < hi) { int mid = (lo + hi) >> 1; if (a[mid] <= key) lo = mid + 1; else hi = mid; }
        } else {
            while (lo < hi) { int mid = (lo + hi) >> 1; if (a[mid] <  key) lo = mid + 1; else hi = mid; }
        }
        rank += lo;
    }
    g_rank[r] = rank;
}

// ---------------------------------------------------------------------------
// K4: scatter — read X linearly (coalesced), write to sorted position.
// 4-way grid-stride unroll for memory-level parallelism.
// ---------------------------------------------------------------------------
__global__ void scatter_kernel(const float* __restrict__ X, float* __restrict__ out) {
    const int total = N * ROWLEN;
    int stride = gridDim.x * blockDim.x;
    int idx = blockIdx.x * blockDim.x + threadIdx.x;
    #pragma unroll 4
    for (int u = 0; u < 4; u++) {
        int e = idx + u * stride;
        if (e < total) {
            int row = e / ROWLEN;
            int col = e - row * ROWLEN;
            float v = X[e] * __ldg(&g_keepf[row]);
            out[(long)__ldg(&g_rank[row]) * ROWLEN + col] = v;
        }
    }
}

// ---------------------------------------------------------------------------
extern "C" void kernel_launch(void* const* d_in, const int* in_sizes, int n_in,
                              void* d_out, int out_size) {
    const float* X = (const float*)d_in[0];
    float* out = (float*)d_out;

    int sort_bytes = (int)sizeof(BlockSortT::TempStorage);
    int nms_bytes = (int)sizeof(NmsShared);
    int smem = sort_bytes > nms_bytes ? sort_bytes : nms_bytes;

    static int smem_set = 0;
    if (!smem_set) {
        cudaFuncSetAttribute(sortnms_kernel,
                             cudaFuncAttributeMaxDynamicSharedMemorySize, smem);
        smem_set = 1;
    }

    score_kernel<<<N / 8, 256>>>(X);
    sortnms_kernel<<<NCLS + NQ, FT, smem>>>(X);
    rank_kernel<<<N / 256, 256>>>();

    const int total = N * ROWLEN;
    const int threads = (total + 3) / 4;
    scatter_kernel<<<(threads + 255) / 256, 256>>>(X, out);
}

// round 8
// speedup vs baseline: 1.1309x; 1.1309x over previous
#include <cuda_runtime.h>
#include <cuda_bf16.h>
#include <cub/block/block_radix_sort.cuh>

#define N 8192
#define ROWLEN 85
#define NCLS 80
#define CAP 512
#define MW 16            // CAP/32 suppression-mask words
#define FT 512           // threads per block
#define NQ 4             // sort quarters
#define QS 2048          // rows per quarter
#define NBLK 100         // 4 sort + 80 nms + 16 rank (single wave: 100 < 148 SMs)

__device__ unsigned g_skey[N];          // ~float_bits(score); asc == score desc
__device__ unsigned g_pack[N];          // row<<7 | cat
__device__ unsigned g_qkeys[NQ * QS];   // per-quarter sorted keys (ascending)
__device__ int g_qpos[N];               // row -> position within its quarter
__device__ int g_rank[N];               // row -> global sorted position
__device__ float g_keepf[N];            // keep flag by original row
__device__ unsigned long long g_tick;   // monotone ticket counter (epochs)
__device__ unsigned long long g_c1;     // score-done arrivals
__device__ unsigned long long g_cs;     // quarter-sort-done arrivals
__device__ unsigned long long g_c2;     // phase-2-done arrivals

typedef cub::BlockRadixSort<unsigned, FT, QS / FT, unsigned, 5> BlockSortT;

struct NmsShared {
    unsigned long long keys[CAP];
    float4 box[CAP];
    float area[CAP];
    unsigned mask[CAP * MW];
    unsigned sup[MW];
    int cnt;
};

// Block-level arrive + spin barrier on a monotone counter (replay-safe:
// targets are epoch-scaled, counters never reset).
__device__ __forceinline__ void gsync(unsigned long long* c, unsigned long long tgt) {
    __syncthreads();
    if (threadIdx.x == 0) {
        __threadfence();
        atomicAdd(c, 1ull);
        while (*(volatile unsigned long long*)c < tgt) {}
        __threadfence();
    }
    __syncthreads();
}

__global__ void __launch_bounds__(FT, 1)
yolonms_kernel(const float* __restrict__ X, float* __restrict__ out) {
    extern __shared__ __align__(16) char sm[];
    __shared__ unsigned long long s_ep;

    int t = threadIdx.x, b = blockIdx.x;
    int lane = t & 31, w = t >> 5;

    // Epoch: blocks of one launch consume NBLK consecutive tickets (launches
    // on a stream serialize), so ticket/NBLK is identical across the launch.
    if (t == 0) s_ep = atomicAdd(&g_tick, 1ull) / NBLK;
    __syncthreads();
    unsigned long long ep = s_ep;

    // ---------------- Phase 1: score (all blocks) ----------------
    // warp per row: class argmax + combined score -> (key, row|cat).
    for (int r = b * 16 + w; r < N; r += NBLK * 16) {
        const float* row = X + (long)r * ROWLEN;
        float v0 = row[5 + lane];
        float v1 = row[37 + lane];
        float v2 = (lane < 16) ? row[69 + lane] : -1.0f;
        float best = v0; int bi = lane;
        if (v1 > best) { best = v1; bi = lane + 32; }
        if (v2 > best) { best = v2; bi = lane + 64; }

        unsigned bb = __float_as_uint(best);           // nonneg -> monotone
        unsigned vmax = __reduce_max_sync(0xffffffffu, bb);
        int cand = (bb == vmax) ? bi : 0x7fffffff;     // smallest idx wins ties
        int bimin = __reduce_min_sync(0xffffffffu, cand);
        if (lane == 0) {
            float score = row[4] * __uint_as_float(vmax);   // in [0, 1)
            g_skey[r] = ~__float_as_uint(score);
            g_pack[r] = ((unsigned)r << 7) | (unsigned)bimin;
        }
    }
    gsync(&g_c1, (ep + 1) * NBLK);

    // ---------------- Phase 2: role-specialized blocks ----------------
    if (b < NQ) {
        // quarter sort: stable LSD radix, 30 significant bits, 6 passes of 5
        const int IPT = QS / FT;
        int qbase = b * QS;
        BlockSortT::TempStorage& temp =
            *reinterpret_cast<BlockSortT::TempStorage*>(sm);
        unsigned keys[IPT], vals[IPT];
        #pragma unroll
        for (int l = 0; l < IPT; l++) {
            int r = qbase + t * IPT + l;
            keys[l] = g_skey[r];
            vals[l] = g_pack[r];
        }
        BlockSortT(temp).Sort(keys, vals, 0, 30);
        #pragma unroll
        for (int l = 0; l < IPT; l++) {
            int p = t * IPT + l;
            g_qkeys[b * QS + p] = keys[l];
            g_qpos[vals[l] >> 7] = p;
        }
        __syncthreads();
        if (t == 0) { __threadfence(); atomicAdd(&g_cs, 1ull); }
    } else if (b < NQ + NCLS) {
        // per-class greedy NMS. Class offsets in the reference make cross-
        // class IoU exactly 0, so suppression decomposes per class.
        NmsShared& S = *reinterpret_cast<NmsShared*>(sm);
        unsigned c = b - NQ;

        if (t == 0) S.cnt = 0;
        S.keys[t] = 0xFFFFFFFFFFFFFFFFull;
        __syncthreads();

        #pragma unroll
        for (int q = 0; q < N / FT; q++) {
            int r = q * FT + t;
            unsigned p = g_pack[r];
            if ((p & 127u) == c) {
                int slot = atomicAdd(&S.cnt, 1);
                if (slot < CAP)
                    S.keys[slot] = ((unsigned long long)g_skey[r] << 32) | p;
            }
        }
        __syncthreads();
        int m = min(S.cnt, CAP);
        int mw = (m + 31) >> 5;

        int p2 = 2;
        while (p2 < m) p2 <<= 1;

        // bitonic sort (asc == score desc, stable by embedded row index)
        for (int k = 2; k <= p2; k <<= 1) {
            for (int j = k >> 1; j > 0; j >>= 1) {
                if (t < (p2 >> 1)) {
                    int i = ((t & ~(j - 1)) << 1) | (t & (j - 1));
                    bool up = ((i & k) == 0);
                    unsigned long long a = S.keys[i], bb2 = S.keys[i | j];
                    if ((a > bb2) == up) { S.keys[i] = bb2; S.keys[i | j] = a; }
                }
                __syncthreads();
            }
        }

        if (t < m) {
            int idx = (int)(((unsigned)(S.keys[t] & 0xFFFFFFFFull)) >> 7);
            const float* row = X + (long)idx * ROWLEN;
            float x1 = row[0], y1 = row[1], x2 = row[2], y2 = row[3];
            S.box[t] = make_float4(x1, y1, x2, y2);
            S.area[t] = (x2 - x1) * (y2 - y1);
        }
        for (int p = t; p < m * MW; p += FT) S.mask[p] = 0u;
        __syncthreads();

        for (int i = w; i < m; i += FT / 32) {
            float4 bi = S.box[i];
            float ai = S.area[i];
            for (int j = i + 1 + lane; j < m; j += 32) {
                float4 bj = S.box[j];
                float xx1 = fmaxf(bi.x, bj.x);
                float yy1 = fmaxf(bi.y, bj.y);
                float xx2 = fminf(bi.z, bj.z);
                float yy2 = fminf(bi.w, bj.w);
                float ww = fmaxf(xx2 - xx1, 0.0f);
                float hh = fmaxf(yy2 - yy1, 0.0f);
                float inter = ww * hh;
                float iou = inter / (ai + S.area[j] - inter);
                if (iou > 0.5f) atomicOr(&S.mask[i * MW + (j >> 5)], 1u << (j & 31));
            }
        }
        __syncthreads();

        if (w == 0) {   // serial greedy bit-merge, lane l owns sup word l
            unsigned sw = 0;
            for (int i = 0; i < m; i++) {
                unsigned word = __shfl_sync(0xffffffffu, sw, i >> 5);
                if (!((word >> (i & 31)) & 1u)) {
                    if (lane < mw) sw |= S.mask[i * MW + lane];
                }
            }
            if (lane < MW) S.sup[lane] = sw;
        }
        __syncthreads();

        if (t < m) {
            int idx = (int)(((unsigned)(S.keys[t] & 0xFFFFFFFFull)) >> 7);
            g_keepf[idx] = ((S.sup[t >> 5] >> (t & 31)) & 1u) ? 0.0f : 1.0f;
        }
    } else {
        // rank blocks: wait for the 4 quarter sorts, then binary-search in smem.
        if (t == 0) {
            while (*(volatile unsigned long long*)&g_cs < (ep + 1) * NQ) {}
            __threadfence();
        }
        __syncthreads();

        unsigned* rk = reinterpret_cast<unsigned*>(sm);
        for (int i = t; i < NQ * QS; i += FT) rk[i] = g_qkeys[i];
        __syncthreads();

        int row = (b - NQ - NCLS) * FT + t;    // one row per thread, 8192 total
        unsigned key = g_skey[row];
        int q = row >> 11;                      // row / QS
        int rank = g_qpos[row];
        // quarters are index-contiguous: q' < q counts <= key, q' > q counts < key
        #pragma unroll
        for (int q2 = 0; q2 < NQ; q2++) {
            if (q2 == q) continue;
            const unsigned* a = rk + q2 * QS;
            int lo = 0, hi = QS;
            if (q2 < q) {
                while (lo < hi) { int mid = (lo + hi) >> 1; if (a[mid] <= key) lo = mid + 1; else hi = mid; }
            } else {
                while (lo < hi) { int mid = (lo + hi) >> 1; if (a[mid] <  key) lo = mid + 1; else hi = mid; }
            }
            rank += lo;
        }
        g_rank[row] = rank;
    }
    gsync(&g_c2, (ep + 1) * NBLK);

    // ---------------- Phase 3: scatter (all blocks) ----------------
    // read X linearly, multiply by keep, write to sorted row position.
    const int total = N * ROWLEN;
    for (int e = b * FT + t; e < total; e += NBLK * FT) {
        int row = e / ROWLEN;
        int col = e - row * ROWLEN;
        float v = X[e] * __ldg(&g_keepf[row]);
        out[(long)__ldg(&g_rank[row]) * ROWLEN + col] = v;
    }
}

// ---------------------------------------------------------------------------
extern "C" void kernel_launch(void* const* d_in, const int* in_sizes, int n_in,
                              void* d_out, int out_size) {
    const float* X = (const float*)d_in[0];
    float* out = (float*)d_out;

    int sort_bytes = (int)sizeof(BlockSortT::TempStorage);
    int nms_bytes = (int)sizeof(NmsShared);
    int rank_bytes = NQ * QS * (int)sizeof(unsigned);
    int smem = sort_bytes;
    if (nms_bytes > smem) smem = nms_bytes;
    if (rank_bytes > smem) smem = rank_bytes;

    static int smem_set = 0;
    if (!smem_set) {
        cudaFuncSetAttribute(yolonms_kernel,
                             cudaFuncAttributeMaxDynamicSharedMemorySize, smem);
        smem_set = 1;
    }

    yolonms_kernel<<<NBLK, FT, smem>>>(X, out);
}

// round 9
// speedup vs baseline: 1.2039x; 1.0645x over previous
#include <cuda_runtime.h>
#include <cuda_bf16.h>

#define N 8192
#define ROWLEN 85
#define NCLS 80
#define CAP 512
#define MW 16              // CAP/32 suppression-mask words
#define FT 512             // threads per block
#define NBLK 144           // 80 NMS + 64 rank; single wave (144 < 148 SMs)
#define RB 64              // rank blocks (ids 80..143)
#define SCANB 32           // first 32 rank blocks run the bin scan
#define BINS 16384         // bin = (key>>16) - 0xC080  (scores in [0,1))
#define ROWS_PER_RB (N / RB)   // 128

__device__ unsigned g_skey[N];          // ~float_bits(score); asc == score desc
__device__ unsigned g_pack[N];          // row<<7 | cat
__device__ unsigned g_hist[BINS];       // bin counts   (zeroed in P3 for next epoch)
__device__ unsigned g_cnt2[BINS];       // scatter cursors (zeroed in P3)
__device__ unsigned g_prefix[BINS];     // exclusive bin prefix (overwritten per epoch)
__device__ unsigned g_chunkTot[SCANB];  // per-chunk totals (overwritten per epoch)
__device__ unsigned g_bkey[N];          // bucketed keys
__device__ int g_brow[N];               // bucketed rows
__device__ int g_rank[N];               // row -> global sorted position
__device__ float g_keepf[N];            // keep flag by original row
__device__ unsigned long long g_tick;   // monotone ticket counter (epochs)
__device__ unsigned long long g_c1;     // P1 done (all 144)
__device__ unsigned long long g_r1, g_r2, g_r3;   // rank-internal (64)
__device__ unsigned long long g_c2;     // P2 done (all 144)

struct NmsShared {
    unsigned long long keys[CAP];
    float4 box[CAP];
    float area[CAP];
    unsigned mask[CAP * MW];
    unsigned sup[MW];
    int cnt;
};

// arrive + spin barrier on a monotone counter (replay-safe: epoch-scaled targets)
__device__ __forceinline__ void gsync(unsigned long long* c, unsigned long long tgt) {
    __syncthreads();
    if (threadIdx.x == 0) {
        __threadfence();
        atomicAdd(c, 1ull);
        while (*(volatile unsigned long long*)c < tgt) {}
        __threadfence();
    }
    __syncthreads();
}

__global__ void __launch_bounds__(FT, 1)
yolonms_kernel(const float* __restrict__ X, float* __restrict__ out) {
    extern __shared__ __align__(16) char sm[];
    __shared__ unsigned long long s_ep;
    __shared__ unsigned s_scan[FT];

    int t = threadIdx.x, b = blockIdx.x;
    int lane = t & 31, w = t >> 5;

    if (t == 0) s_ep = atomicAdd(&g_tick, 1ull) / NBLK;
    __syncthreads();
    unsigned long long ep = s_ep;

    // ---------------- Phase 1: score + histogram (all blocks) ----------------
    for (int r = b * 16 + w; r < N; r += NBLK * 16) {
        const float* row = X + (long)r * ROWLEN;
        float v0 = row[5 + lane];
        float v1 = row[37 + lane];
        float v2 = (lane < 16) ? row[69 + lane] : -1.0f;
        float best = v0; int bi = lane;
        if (v1 > best) { best = v1; bi = lane + 32; }
        if (v2 > best) { best = v2; bi = lane + 64; }

        unsigned bb = __float_as_uint(best);            // nonneg -> monotone
        unsigned vmax = __reduce_max_sync(0xffffffffu, bb);
        int cand = (bb == vmax) ? bi : 0x7fffffff;      // smallest idx wins ties
        int bimin = __reduce_min_sync(0xffffffffu, cand);
        if (lane == 0) {
            float score = row[4] * __uint_as_float(vmax);   // in [0, 1)
            unsigned key = ~__float_as_uint(score);
            g_skey[r] = key;
            g_pack[r] = ((unsigned)r << 7) | (unsigned)bimin;
            atomicAdd(&g_hist[(key >> 16) - 0xC080u], 1u);
        }
    }
    gsync(&g_c1, (ep + 1) * NBLK);

    // ---------------- Phase 2: NMS blocks || rank blocks ----------------
    if (b < NCLS) {
        // per-class greedy NMS. Class offsets in the reference make cross-
        // class IoU exactly 0, so suppression decomposes per class.
        NmsShared& S = *reinterpret_cast<NmsShared*>(sm);
        unsigned c = b;

        if (t == 0) S.cnt = 0;
        S.keys[t] = 0xFFFFFFFFFFFFFFFFull;
        __syncthreads();

        #pragma unroll
        for (int q = 0; q < N / FT; q++) {
            int r = q * FT + t;
            unsigned p = g_pack[r];
            if ((p & 127u) == c) {
                int slot = atomicAdd(&S.cnt, 1);
                if (slot < CAP)
                    S.keys[slot] = ((unsigned long long)g_skey[r] << 32) | p;
            }
        }
        __syncthreads();
        int m = min(S.cnt, CAP);
        int mw = (m + 31) >> 5;

        int p2 = 2;
        while (p2 < m) p2 <<= 1;

        // bitonic sort (asc == score desc, stable by embedded row index)
        for (int k = 2; k <= p2; k <<= 1) {
            for (int j = k >> 1; j > 0; j >>= 1) {
                if (t < (p2 >> 1)) {
                    int i = ((t & ~(j - 1)) << 1) | (t & (j - 1));
                    bool up = ((i & k) == 0);
                    unsigned long long a = S.keys[i], bb2 = S.keys[i | j];
                    if ((a > bb2) == up) { S.keys[i] = bb2; S.keys[i | j] = a; }
                }
                __syncthreads();
            }
        }

        if (t < m) {
            int idx = (int)(((unsigned)(S.keys[t] & 0xFFFFFFFFull)) >> 7);
            const float* row = X + (long)idx * ROWLEN;
            float x1 = row[0], y1 = row[1], x2 = row[2], y2 = row[3];
            S.box[t] = make_float4(x1, y1, x2, y2);
            S.area[t] = (x2 - x1) * (y2 - y1);
        }
        for (int p = t; p < m * MW; p += FT) S.mask[p] = 0u;
        __syncthreads();

        // mask[i] = { j > i : IoU(i,j) > 0.5 } — fully parallel
        for (int i = w; i < m; i += FT / 32) {
            float4 bi = S.box[i];
            float ai = S.area[i];
            for (int j = i + 1 + lane; j < m; j += 32) {
                float4 bj = S.box[j];
                float xx1 = fmaxf(bi.x, bj.x);
                float yy1 = fmaxf(bi.y, bj.y);
                float xx2 = fminf(bi.z, bj.z);
                float yy2 = fminf(bi.w, bj.w);
                float ww = fmaxf(xx2 - xx1, 0.0f);
                float hh = fmaxf(yy2 - yy1, 0.0f);
                float inter = ww * hh;
                float iou = inter / (ai + S.area[j] - inter);
                if (iou > 0.5f) atomicOr(&S.mask[i * MW + (j >> 5)], 1u << (j & 31));
            }
        }
        __syncthreads();

        if (w == 0) {   // serial greedy bit-merge, lane l owns sup word l
            unsigned sw = 0;
            for (int i = 0; i < m; i++) {
                unsigned word = __shfl_sync(0xffffffffu, sw, i >> 5);
                if (!((word >> (i & 31)) & 1u)) {
                    if (lane < mw) sw |= S.mask[i * MW + lane];
                }
            }
            if (lane < MW) S.sup[lane] = sw;
        }
        __syncthreads();

        if (t < m) {
            int idx = (int)(((unsigned)(S.keys[t] & 0xFFFFFFFFull)) >> 7);
            g_keepf[idx] = ((S.sup[t >> 5] >> (t & 31)) & 1u) ? 0.0f : 1.0f;
        }
    } else {
        // ---- rank blocks (80..143): counting-sort rank over 16K bins ----
        int rb = b - NCLS;

        // step A: 32 scan blocks do exclusive scan of their 512-bin chunk
        unsigned excl = 0, val = 0;
        if (rb < SCANB) {
            int bin = rb * (BINS / SCANB) + t;      // 512 bins per chunk
            val = g_hist[bin];
            s_scan[t] = val;
            __syncthreads();
            unsigned acc = val;
            #pragma unroll
            for (int off = 1; off < FT; off <<= 1) {
                unsigned u = (t >= off) ? s_scan[t - off] : 0u;
                __syncthreads();
                acc += u;
                s_scan[t] = acc;
                __syncthreads();
            }
            excl = acc - val;
            if (t == FT - 1) g_chunkTot[rb] = acc;
        }
        gsync(&g_r1, (ep + 1) * RB);

        // step B: add chunk bases, publish prefix
        if (rb < SCANB) {
            unsigned basesum = 0;
            #pragma unroll
            for (int cc = 0; cc < SCANB; cc++) {
                unsigned v = g_chunkTot[cc];
                if (cc < rb) basesum += v;
            }
            g_prefix[rb * (BINS / SCANB) + t] = basesum + excl;
        }
        gsync(&g_r2, (ep + 1) * RB);

        // step C: bucket scatter (128 rows per rank block)
        if (t < ROWS_PER_RB) {
            int r = rb * ROWS_PER_RB + t;
            unsigned key = g_skey[r];
            unsigned bin = (key >> 16) - 0xC080u;
            unsigned slot = g_prefix[bin] + atomicAdd(&g_cnt2[bin], 1u);
            g_bkey[slot] = key;
            g_brow[slot] = r;
        }
        gsync(&g_r3, (ep + 1) * RB);

        // step D: within-bucket exact rank by (key asc, row asc)
        if (t < ROWS_PER_RB) {
            int s = rb * ROWS_PER_RB + t;
            unsigned key = g_bkey[s];
            int row = g_brow[s];
            unsigned bin = (key >> 16) - 0xC080u;
            unsigned start = g_prefix[bin];
            unsigned len = g_hist[bin];
            int cnt = 0;
            for (unsigned i = start; i < start + len; i++) {
                unsigned k2 = g_bkey[i];
                if (k2 < key || (k2 == key && g_brow[i] < row)) cnt++;
            }
            g_rank[row] = (int)start + cnt;
        }
    }
    gsync(&g_c2, (ep + 1) * NBLK);

    // ---------------- Phase 3: output scatter + reset for next epoch ----------------
    {
        int i = b * FT + t;
        if (i < BINS) { g_hist[i] = 0u; g_cnt2[i] = 0u; }
    }
    const int total = N * ROWLEN;
    for (int e = b * FT + t; e < total; e += NBLK * FT) {
        int row = e / ROWLEN;
        int col = e - row * ROWLEN;
        float v = X[e] * __ldg(&g_keepf[row]);
        out[(long)__ldg(&g_rank[row]) * ROWLEN + col] = v;
    }
}

// ---------------------------------------------------------------------------
extern "C" void kernel_launch(void* const* d_in, const int* in_sizes, int n_in,
                              void* d_out, int out_size) {
    const float* X = (const float*)d_in[0];
    float* out = (float*)d_out;

    int smem = (int)sizeof(NmsShared);
    static int smem_set = 0;
    if (!smem_set) {
        cudaFuncSetAttribute(yolonms_kernel,
                             cudaFuncAttributeMaxDynamicSharedMemorySize, smem);
        smem_set = 1;
    }

    yolonms_kernel<<<NBLK, FT, smem>>>(X, out);
}

// round 10
// speedup vs baseline: 1.3743x; 1.1415x over previous
#include <cuda_runtime.h>
#include <cuda_bf16.h>

#define N 8192
#define ROWLEN 85
#define NCLS 80
#define CAP 256
#define MW 8               // CAP/32 suppression-mask words
#define FT 1024            // threads per block
#define NBLK 144           // 80 NMS + 64 rank; single wave, 1 block/SM
#define RB 64              // rank blocks (ids 80..143)
#define SCANB 32           // first 32 rank blocks scan 512 bins each
#define BINS 16384         // bin = (key>>16) - 0xC080  (scores in [0,1))
#define ROWS_PER_RB (N / RB)   // 128

__device__ unsigned g_skey[N];          // ~float_bits(score); asc == score desc
__device__ unsigned g_pack[N];          // row<<7 | cat
__device__ unsigned g_hist[BINS];       // bin counts (zeroed in P3 for next epoch)
__device__ unsigned g_cnt2[BINS];       // scatter cursors (zeroed in P3)
__device__ unsigned g_prefix[BINS];     // exclusive bin prefix
__device__ unsigned g_chunkTot[SCANB];  // per-chunk totals
__device__ unsigned g_bkey[N];          // bucketed keys
__device__ int g_brow[N];               // bucketed rows
__device__ int g_rank[N];               // row -> global sorted position
__device__ float g_keepf[N];            // keep flag by original row
__device__ unsigned long long g_tick;   // monotone ticket counter (epochs)
__device__ unsigned long long g_c1;     // P1 done (144)
__device__ unsigned long long g_r1, g_r2, g_r3;   // rank-internal (64)
__device__ unsigned long long g_c2;     // P2 done (144)

struct NmsShared {
    unsigned long long keys[CAP];    // compacted (unsorted)
    unsigned long long skeys[CAP];   // counting-sorted
    float4 box[CAP];
    float area[CAP];
    unsigned mask[CAP * MW];
    unsigned sup[MW];
    int cnt;
};

// arrive + spin barrier on a monotone counter (replay-safe: epoch-scaled targets)
__device__ __forceinline__ void gsync(unsigned long long* c, unsigned long long tgt) {
    __syncthreads();
    if (threadIdx.x == 0) {
        __threadfence();
        atomicAdd(c, 1ull);
        while (*(volatile unsigned long long*)c < tgt) {}
        __threadfence();
    }
    __syncthreads();
}

__global__ void __launch_bounds__(FT, 1)
yolonms_kernel(const float* __restrict__ X, float* __restrict__ out) {
    extern __shared__ __align__(16) char sm[];
    __shared__ unsigned long long s_ep;
    __shared__ unsigned s_ws[32];

    int t = threadIdx.x, b = blockIdx.x;
    int lane = t & 31, w = t >> 5;

    if (t == 0) s_ep = atomicAdd(&g_tick, 1ull) / NBLK;
    __syncthreads();
    unsigned long long ep = s_ep;

    // ---------------- Phase 1: score + histogram (all blocks, 32 warps) ----------------
    for (int r = b * 32 + w; r < N; r += NBLK * 32) {
        const float* row = X + (long)r * ROWLEN;
        float v0 = row[5 + lane];
        float v1 = row[37 + lane];
        float v2 = (lane < 16) ? row[69 + lane] : -1.0f;
        float best = v0; int bi = lane;
        if (v1 > best) { best = v1; bi = lane + 32; }
        if (v2 > best) { best = v2; bi = lane + 64; }

        unsigned bb = __float_as_uint(best);            // nonneg -> monotone
        unsigned vmax = __reduce_max_sync(0xffffffffu, bb);
        int cand = (bb == vmax) ? bi : 0x7fffffff;      // smallest idx wins ties
        int bimin = __reduce_min_sync(0xffffffffu, cand);
        if (lane == 0) {
            float score = row[4] * __uint_as_float(vmax);   // in [0, 1)
            unsigned key = ~__float_as_uint(score);
            g_skey[r] = key;
            g_pack[r] = ((unsigned)r << 7) | (unsigned)bimin;
            unsigned bin = (key >> 16) - 0xC080u;
            if (bin >= BINS) bin = BINS - 1;
            atomicAdd(&g_hist[bin], 1u);
        }
    }
    gsync(&g_c1, (ep + 1) * NBLK);

    // ---------------- Phase 2: NMS blocks || rank blocks ----------------
    if (b < NCLS) {
        // per-class greedy NMS. Class offsets in the reference make cross-
        // class IoU exactly 0, so suppression decomposes per class.
        NmsShared& S = *reinterpret_cast<NmsShared*>(sm);
        unsigned c = b;

        if (t == 0) S.cnt = 0;
        __syncthreads();

        #pragma unroll
        for (int q = 0; q < N / FT; q++) {
            int r = q * FT + t;
            unsigned p = g_pack[r];
            if ((p & 127u) == c) {
                int slot = atomicAdd(&S.cnt, 1);
                if (slot < CAP)
                    S.keys[slot] = ((unsigned long long)g_skey[r] << 32) | p;
            }
        }
        __syncthreads();
        int m = min(S.cnt, CAP);
        int mw = (m + 31) >> 5;

        // counting sort: keys unique (row embedded) -> exact permutation.
        // asc key == score desc, ties by ascending row (== stable argsort).
        if (t < m) {
            unsigned long long k = S.keys[t];
            int r = 0;
            for (int j = 0; j < m; j++) r += (S.keys[j] < k);
            S.skeys[r] = k;
        }
        __syncthreads();

        if (t < m) {
            int idx = (int)(((unsigned)(S.skeys[t] & 0xFFFFFFFFull)) >> 7);
            const float* row = X + (long)idx * ROWLEN;
            float x1 = row[0], y1 = row[1], x2 = row[2], y2 = row[3];
            S.box[t] = make_float4(x1, y1, x2, y2);
            S.area[t] = (x2 - x1) * (y2 - y1);
        }
        for (int p = t; p < m * MW; p += FT) S.mask[p] = 0u;
        __syncthreads();

        // mask[i] = { j > i : IoU(i,j) > 0.5 } — fully parallel over 32 warps
        for (int i = w; i < m; i += FT / 32) {
            float4 bi = S.box[i];
            float ai = S.area[i];
            for (int j = i + 1 + lane; j < m; j += 32) {
                float4 bj = S.box[j];
                float xx1 = fmaxf(bi.x, bj.x);
                float yy1 = fmaxf(bi.y, bj.y);
                float xx2 = fminf(bi.z, bj.z);
                float yy2 = fminf(bi.w, bj.w);
                float ww = fmaxf(xx2 - xx1, 0.0f);
                float hh = fmaxf(yy2 - yy1, 0.0f);
                float inter = ww * hh;
                float iou = inter / (ai + S.area[j] - inter);
                if (iou > 0.5f) atomicOr(&S.mask[i * MW + (j >> 5)], 1u << (j & 31));
            }
        }
        __syncthreads();

        // serial greedy bit-merge, single thread, unconditional prefetch:
        // loads never depend on sup state -> dependent chain is select+OR only.
        if (t == 0) {
            unsigned sx[MW];
            #pragma unroll
            for (int q = 0; q < MW; q++) sx[q] = 0u;
            unsigned pm[MW];
            #pragma unroll
            for (int q = 0; q < MW; q++) pm[q] = S.mask[q];
            for (int i = 0; i < m; i++) {
                unsigned nm[MW];
                #pragma unroll
                for (int q = 0; q < MW; q++) nm[q] = S.mask[(i + 1) * MW + q];
                unsigned kept = ((sx[i >> 5] >> (i & 31)) & 1u) ^ 1u;
                unsigned sel = 0u - kept;          // all-ones if kept
                #pragma unroll
                for (int q = 0; q < MW; q++) sx[q] |= (pm[q] & sel);
                #pragma unroll
                for (int q = 0; q < MW; q++) pm[q] = nm[q];
            }
            #pragma unroll
            for (int q = 0; q < MW; q++) S.sup[q] = sx[q];
        }
        __syncthreads();
        (void)mw;

        if (t < m) {
            int idx = (int)(((unsigned)(S.skeys[t] & 0xFFFFFFFFull)) >> 7);
            g_keepf[idx] = ((S.sup[t >> 5] >> (t & 31)) & 1u) ? 0.0f : 1.0f;
        }
    } else {
        // ---- rank blocks (80..143): counting-sort rank over 16K bins ----
        int rb = b - NCLS;

        // step A: 32 scan blocks, 512 bins each, warp-shuffle scan
        unsigned v = 0, incl = 0;
        if (rb < SCANB && t < 512) {
            int bin = rb * 512 + t;
            v = g_hist[bin];
            incl = v;
            #pragma unroll
            for (int off = 1; off < 32; off <<= 1) {
                unsigned u = __shfl_up_sync(0xffffffffu, incl, off);
                if (lane >= off) incl += u;
            }
            if (lane == 31) s_ws[w] = incl;     // 16 warp sums
        }
        __syncthreads();
        if (rb < SCANB && t < 32) {
            unsigned x = (lane < 16) ? s_ws[lane] : 0u;
            #pragma unroll
            for (int off = 1; off < 32; off <<= 1) {
                unsigned u = __shfl_up_sync(0xffffffffu, x, off);
                if (lane >= off) x += u;
            }
            if (lane < 16) s_ws[lane] = x;       // inclusive warp-sum scan
            if (lane == 15 && rb < SCANB) g_chunkTot[rb] = x;
        }
        __syncthreads();
        unsigned excl_chunk = 0;
        if (rb < SCANB && t < 512) {
            unsigned wbase = (w > 0) ? s_ws[w - 1] : 0u;
            excl_chunk = wbase + incl - v;       // exclusive within chunk
        }
        gsync(&g_r1, (ep + 1) * RB);

        // step B: add chunk bases, publish global prefix
        if (rb < SCANB && t < 512) {
            unsigned basesum = 0;
            #pragma unroll
            for (int cc = 0; cc < SCANB; cc++) {
                unsigned cv = g_chunkTot[cc];
                if (cc < rb) basesum += cv;
            }
            g_prefix[rb * 512 + t] = basesum + excl_chunk;
        }
        gsync(&g_r2, (ep + 1) * RB);

        // step C: bucket scatter (128 rows per rank block)
        if (t < ROWS_PER_RB) {
            int r = rb * ROWS_PER_RB + t;
            unsigned key = g_skey[r];
            unsigned bin = (key >> 16) - 0xC080u;
            if (bin >= BINS) bin = BINS - 1;
            unsigned slot = g_prefix[bin] + atomicAdd(&g_cnt2[bin], 1u);
            g_bkey[slot] = key;
            g_brow[slot] = r;
        }
        gsync(&g_r3, (ep + 1) * RB);

        // step D: within-bucket exact rank by (key asc, row asc)
        if (t < ROWS_PER_RB) {
            int s = rb * ROWS_PER_RB + t;
            unsigned key = g_bkey[s];
            int row = g_brow[s];
            unsigned bin = (key >> 16) - 0xC080u;
            if (bin >= BINS) bin = BINS - 1;
            unsigned start = g_prefix[bin];
            unsigned len = g_hist[bin];
            int cnt = 0;
            for (unsigned i = start; i < start + len; i++) {
                unsigned k2 = g_bkey[i];
                if (k2 < key || (k2 == key && g_brow[i] < row)) cnt++;
            }
            g_rank[row] = (int)start + cnt;
        }
    }
    gsync(&g_c2, (ep + 1) * NBLK);

    // ---------------- Phase 3: output scatter + reset for next epoch ----------------
    {
        int i = b * FT + t;
        if (i < BINS) { g_hist[i] = 0u; g_cnt2[i] = 0u; }
    }
    const int total = N * ROWLEN;
    for (int e = b * FT + t; e < total; e += NBLK * FT) {
        int row = e / ROWLEN;
        int col = e - row * ROWLEN;
        float v = X[e] * __ldg(&g_keepf[row]);
        out[(long)__ldg(&g_rank[row]) * ROWLEN + col] = v;
    }
}

// ---------------------------------------------------------------------------
extern "C" void kernel_launch(void* const* d_in, const int* in_sizes, int n_in,
                              void* d_out, int out_size) {
    const float* X = (const float*)d_in[0];
    float* out = (float*)d_out;

    int smem = (int)sizeof(NmsShared);
    static int smem_set = 0;
    if (!smem_set) {
        cudaFuncSetAttribute(yolonms_kernel,
                             cudaFuncAttributeMaxDynamicSharedMemorySize, smem);
        smem_set = 1;
    }

    yolonms_kernel<<<NBLK, FT, smem>>>(X, out);
}